// round 6
// baseline (speedup 1.0000x reference)
#include <cuda_runtime.h>
#include <cstdint>

// ---------------------------------------------------------------------------
// Problem constants
// ---------------------------------------------------------------------------
#define NSEQ 24
#define NBAT 16
#define NNOD 1024
#define HD   64
#define BH   1024              /* NBAT*HD */
#define TOT  1048576           /* NNOD*BH */

// smem layout (floats)
#define A_ST 20
#define B_ST 136
#define S_ST 136
#define W_ST 264
#define OFF_A   0              /* 2 * 128*20  = 5120  */
#define OFF_B   5120           /* 2 * 16*136  = 4352  -> end 9472 */
#define OFF_WCH 0              /* 32*264 = 8448, overlays A/B after GEMM1 */
#define OFF_SUP 9472           /* 128*136 = 17408 -> end 26880 */
#define OFF_PRM 26880          /* bg 256 | gamma1 64 | beta1 64 = 384 */
#define SMEMF   27264
#define SMEMB   (SMEMF * 4)    /* 109056 bytes */

// ---------------------------------------------------------------------------
// Persistent device scratch (static — no allocation)
// ---------------------------------------------------------------------------
__device__ float g_adj[NNOD * NNOD];                // tf32-rounded normalized adjacency
__device__ float g_wg[2 * 128 * 256];               // tf32-rounded W_g
__device__ float g_z0[(size_t)NSEQ * TOT];          // LN0(xh)+PE+node_embed, (s,n,b,h)
__device__ float g_z1[TOT];                         // LN1(h0_new)+node_embed, (n,b,h)
__device__ float g_h0[2][TOT];                      // ping-pong h, layer 0
__device__ float g_h1[2][TOT];                      // ping-pong h, layer 1
__device__ float g_c0[TOT];
__device__ float g_c1[TOT];

// ---------------------------------------------------------------------------
// Helpers
// ---------------------------------------------------------------------------
__device__ __forceinline__ float tf32r(float f) {
    unsigned u;
    asm("cvt.rna.tf32.f32 %0, %1;" : "=r"(u) : "f"(f));
    return __uint_as_float(u);
}

__device__ __forceinline__ void mma8(float* c, const unsigned* a, const unsigned* b) {
    asm("mma.sync.aligned.m16n8k8.row.col.f32.tf32.tf32.f32 "
        "{%0,%1,%2,%3},{%4,%5,%6,%7},{%8,%9},{%0,%1,%2,%3};"
        : "+f"(c[0]), "+f"(c[1]), "+f"(c[2]), "+f"(c[3])
        : "r"(a[0]), "r"(a[1]), "r"(a[2]), "r"(a[3]), "r"(b[0]), "r"(b[1]));
}

__device__ __forceinline__ float sigm(float x) { return 1.0f / (1.0f + expf(-x)); }

// ---------------------------------------------------------------------------
// Prep kernels
// ---------------------------------------------------------------------------
__global__ void __launch_bounds__(256) adj_norm_kernel(const float* __restrict__ adj) {
    int m = blockIdx.x, tid = threadIdx.x;
    __shared__ float red[8];
    float s = 0.f;
    for (int j = tid; j < NNOD; j += 256) s += adj[m * NNOD + j];
    for (int o = 16; o; o >>= 1) s += __shfl_xor_sync(0xffffffffu, s, o);
    if ((tid & 31) == 0) red[tid >> 5] = s;
    __syncthreads();
    if (tid < 8) {
        float v = red[tid];
        for (int o = 4; o; o >>= 1) v += __shfl_xor_sync(0xffu, v, o);
        if (tid == 0) red[0] = v;
    }
    __syncthreads();
    float inv = 1.0f / (red[0] + 1e-8f);
    for (int j = tid; j < NNOD; j += 256)
        g_adj[m * NNOD + j] = tf32r(adj[m * NNOD + j] * inv);
}

__global__ void __launch_bounds__(256) wgcvt_kernel(const float* __restrict__ Wg) {
    int i = blockIdx.x * 256 + threadIdx.x;
    if (i < 2 * 128 * 256) g_wg[i] = tf32r(Wg[i]);
}

__global__ void __launch_bounds__(256) zero_kernel() {
    int i = blockIdx.x * 256 + threadIdx.x;
    g_h0[0][i] = 0.f; g_h1[0][i] = 0.f; g_c0[i] = 0.f; g_c1[i] = 0.f;
}

// Input projection + sinusoidal PE + layer-0 LayerNorm + node_embed, ALL timesteps.
// One warp per (b,s,n) row. z0[(s*N+n)*B*H + b*H + h]
__global__ void __launch_bounds__(256) proj_kernel(
    const float* __restrict__ x, const float* __restrict__ Win,
    const float* __restrict__ bin, const float* __restrict__ nemb,
    const float* __restrict__ gam, const float* __restrict__ bet)
{
    __shared__ float sW[512];
    __shared__ float sB[64];
    int tid = threadIdx.x;
    sW[tid] = Win[tid];
    sW[tid + 256] = Win[tid + 256];
    if (tid < 64) sB[tid] = bin[tid];
    __syncthreads();

    int rid = blockIdx.x * 8 + (tid >> 5);   // over (b,s,n) in x order
    int lane = tid & 31;
    int n = rid & 1023;
    int s = (rid >> 10) % NSEQ;
    int b = rid / (1024 * NSEQ);

    const float* xr = x + (size_t)rid * 8;
    float xd[8];
#pragma unroll
    for (int d = 0; d < 8; d++) xd[d] = xr[d];

    float v[2];
#pragma unroll
    for (int p = 0; p < 2; p++) {
        int h = lane + 32 * p;
        float acc = sB[h];
#pragma unroll
        for (int d = 0; d < 8; d++) acc = fmaf(xd[d], sW[d * 64 + h], acc);
        int k2 = h & ~1;
        float dv = expf(-(float)k2 * (9.210340371976184f / 64.0f));
        float ang = (float)s * dv;
        acc += (h & 1) ? cosf(ang) : sinf(ang);
        v[p] = acc;
    }
    float s1 = v[0] + v[1], s2 = v[0] * v[0] + v[1] * v[1];
    for (int o = 16; o; o >>= 1) {
        s1 += __shfl_xor_sync(0xffffffffu, s1, o);
        s2 += __shfl_xor_sync(0xffffffffu, s2, o);
    }
    float mean = s1 * (1.0f / 64.0f);
    float var  = s2 * (1.0f / 64.0f) - mean * mean;
    float rs = rsqrtf(var + 1e-5f);
#pragma unroll
    for (int p = 0; p < 2; p++) {
        int h = lane + 32 * p;
        float z = (v[p] - mean) * rs * gam[h] + bet[h] + nemb[n * 64 + h];
        g_z0[(((size_t)s * NNOD + n) * NBAT + b) * HD + h] = z;
    }
}

// ---------------------------------------------------------------------------
// Fused per-(t,layer) kernel.
// grid = (8 m-tiles, 16 batches), 256 threads.
//  GEMM1: sup(128x128) = adj[m-tile,:](tf32) @ [z|h](tf32)   K=1024
//  GEMM2: gates(128x256) = sup(tf32) @ W_g(tf32)             K=128
//  LSTM pointwise + residual + epilogue (LN->z1 for layer0, d_out for layer1)
// ---------------------------------------------------------------------------
template <int LAYER>
__global__ void __launch_bounds__(256) layer_kernel(
    int t, int pp,
    const float* __restrict__ bg_all,
    const float* __restrict__ gam_all, const float* __restrict__ bet_all,
    const float* __restrict__ nemb, float* __restrict__ out)
{
    extern __shared__ float sm[];
    const int tid = threadIdx.x;
    const int lane = tid & 31, wid = tid >> 5;
    const int gid = lane >> 2, tig = lane & 3;
    const int m0 = blockIdx.x * 128;
    const int b  = blockIdx.y;

    const float* zsrc  = (LAYER == 0) ? (g_z0 + (size_t)t * TOT) : g_z1;
    const float* hprev = (LAYER == 0) ? g_h0[pp] : g_h1[pp];
    float* hdst        = (LAYER == 0) ? g_h0[pp ^ 1] : g_h1[pp ^ 1];
    float* cst         = (LAYER == 0) ? g_c0 : g_c1;
    const float* wg    = g_wg + LAYER * (128 * 256);
    const float* bgp_g = bg_all + LAYER * 256;

    // stage small params
    sm[OFF_PRM + tid] = bgp_g[tid];
    if (LAYER == 0 && tid < 128) {
        if (tid < 64) sm[OFF_PRM + 256 + tid] = gam_all[64 + tid];  // gamma layer-1
        else          sm[OFF_PRM + 256 + tid] = bet_all[tid];       // beta  layer-1
    }

    // ---------------- GEMM1 ----------------
    const int ar = tid >> 2;            // 0..63
    const int ac = (tid & 3) * 4;
    const float* pA0 = g_adj + (size_t)(m0 + ar) * NNOD + ac;
    const float* pA1 = pA0 + (size_t)64 * NNOD;
    const int br = tid >> 4;            // 0..15
    const int bc = (tid & 15) * 4;      // 0..60
    const float* pZ = zsrc  + (size_t)br * BH + b * HD + bc;
    const float* pH = hprev + (size_t)br * BH + b * HD + bc;

    float4 ra0 = *(const float4*)pA0;
    float4 ra1 = *(const float4*)pA1;
    float4 rz  = *(const float4*)pZ;
    float4 rh  = *(const float4*)pH;
    {
        float* As = sm + OFF_A;
        float* Bs = sm + OFF_B;
        *(float4*)&As[ar * A_ST + ac] = ra0;
        *(float4*)&As[(ar + 64) * A_ST + ac] = ra1;
        float4 u = make_float4(tf32r(rz.x), tf32r(rz.y), tf32r(rz.z), tf32r(rz.w));
        float4 w = make_float4(tf32r(rh.x), tf32r(rh.y), tf32r(rh.z), tf32r(rh.w));
        *(float4*)&Bs[br * B_ST + bc]      = u;
        *(float4*)&Bs[br * B_ST + 64 + bc] = w;
    }
    __syncthreads();

    float acc[2][8][4];
#pragma unroll
    for (int a = 0; a < 2; a++)
#pragma unroll
        for (int j = 0; j < 8; j++)
#pragma unroll
            for (int e = 0; e < 4; e++) acc[a][j][e] = 0.f;

    const int wm = wid & 3, wn = wid >> 2;
    const int mrow = wm * 32, ncol = wn * 64;

#pragma unroll 1
    for (int kt = 0; kt < 64; ++kt) {
        if (kt < 63) {
            int ko = (kt + 1) * 16;
            ra0 = *(const float4*)(pA0 + ko);
            ra1 = *(const float4*)(pA1 + ko);
            rz  = *(const float4*)(pZ + (size_t)ko * BH);
            rh  = *(const float4*)(pH + (size_t)ko * BH);
        }
        const float* As = sm + OFF_A + (kt & 1) * (128 * A_ST);
        const float* Bs = sm + OFF_B + (kt & 1) * (16 * B_ST);
#pragma unroll
        for (int kk = 0; kk < 2; ++kk) {
            const int kb = kk * 8;
            unsigned af[2][4];
#pragma unroll
            for (int a = 0; a < 2; a++) {
                int r = mrow + a * 16 + gid;
                af[a][0] = __float_as_uint(As[r * A_ST + kb + tig]);
                af[a][1] = __float_as_uint(As[(r + 8) * A_ST + kb + tig]);
                af[a][2] = __float_as_uint(As[r * A_ST + kb + tig + 4]);
                af[a][3] = __float_as_uint(As[(r + 8) * A_ST + kb + tig + 4]);
            }
#pragma unroll
            for (int j = 0; j < 8; j++) {
                unsigned bf[2];
                int c = ncol + j * 8 + gid;
                bf[0] = __float_as_uint(Bs[(kb + tig) * B_ST + c]);
                bf[1] = __float_as_uint(Bs[(kb + tig + 4) * B_ST + c]);
                mma8(acc[0][j], af[0], bf);
                mma8(acc[1][j], af[1], bf);
            }
        }
        if (kt < 63) {
            float* Asn = sm + OFF_A + ((kt + 1) & 1) * (128 * A_ST);
            float* Bsn = sm + OFF_B + ((kt + 1) & 1) * (16 * B_ST);
            *(float4*)&Asn[ar * A_ST + ac] = ra0;
            *(float4*)&Asn[(ar + 64) * A_ST + ac] = ra1;
            float4 u = make_float4(tf32r(rz.x), tf32r(rz.y), tf32r(rz.z), tf32r(rz.w));
            float4 w = make_float4(tf32r(rh.x), tf32r(rh.y), tf32r(rh.z), tf32r(rh.w));
            *(float4*)&Bsn[br * B_ST + bc]      = u;
            *(float4*)&Bsn[br * B_ST + 64 + bc] = w;
            __syncthreads();
        }
    }

    // store sup (tf32-rounded) to smem
    float* Ss = sm + OFF_SUP;
#pragma unroll
    for (int a = 0; a < 2; a++)
#pragma unroll
        for (int j = 0; j < 8; j++) {
            int r = mrow + a * 16 + gid;
            int c = ncol + j * 8 + tig * 2;
            *(float2*)&Ss[r * S_ST + c]       = make_float2(tf32r(acc[a][j][0]), tf32r(acc[a][j][1]));
            *(float2*)&Ss[(r + 8) * S_ST + c] = make_float2(tf32r(acc[a][j][2]), tf32r(acc[a][j][3]));
        }

    // ---------------- GEMM2 ----------------
    float acc2[32][4];
#pragma unroll
    for (int j = 0; j < 32; j++)
#pragma unroll
        for (int e = 0; e < 4; e++) acc2[j][e] = 0.f;

    const int w2row = wid * 16;
    float* Wc = sm + OFF_WCH;

#pragma unroll 1
    for (int kc = 0; kc < 4; ++kc) {
        __syncthreads();   // prior chunk consumed / GEMM1 bufs free / sup visible
#pragma unroll
        for (int i = 0; i < 8; i++) {
            int q = tid + i * 256;
            int r = q >> 6, c = (q & 63) * 4;
            *(float4*)&Wc[r * W_ST + c] = *(const float4*)&wg[(kc * 32 + r) * 256 + c];
        }
        __syncthreads();
#pragma unroll
        for (int kk = 0; kk < 4; ++kk) {
            const int kb = kk * 8;
            unsigned af[4];
            int rr = w2row + gid;
            int ks = kc * 32 + kb;
            af[0] = __float_as_uint(Ss[rr * S_ST + ks + tig]);
            af[1] = __float_as_uint(Ss[(rr + 8) * S_ST + ks + tig]);
            af[2] = __float_as_uint(Ss[rr * S_ST + ks + tig + 4]);
            af[3] = __float_as_uint(Ss[(rr + 8) * S_ST + ks + tig + 4]);
#pragma unroll
            for (int j = 0; j < 32; j++) {
                unsigned bf[2];
                int c = j * 8 + gid;
                bf[0] = __float_as_uint(Wc[(kb + tig) * W_ST + c]);
                bf[1] = __float_as_uint(Wc[(kb + tig + 4) * W_ST + c]);
                mma8(acc2[j], af, bf);
            }
        }
    }

    // ---------------- LSTM pointwise + epilogue ----------------
    const float* bgs = sm + OFF_PRM;
    float hv[2][8][2];

#pragma unroll
    for (int j2 = 0; j2 < 8; ++j2) {
        int hc = j2 * 8 + tig * 2;
#pragma unroll
        for (int a = 0; a < 2; ++a) {
            int r = w2row + gid + a * 8;
            int n = m0 + r;
            size_t base = ((size_t)n * NBAT + b) * HD + hc;
            float2 cp = *(const float2*)&cst[base];
            float cn[2], hn[2];
#pragma unroll
            for (int e = 0; e < 2; ++e) {
                float ig = acc2[j2][a * 2 + e]      + bgs[hc + e];
                float fg = acc2[j2 + 8][a * 2 + e]  + bgs[64 + hc + e];
                float gg = acc2[j2 + 16][a * 2 + e] + bgs[128 + hc + e];
                float og = acc2[j2 + 24][a * 2 + e] + bgs[192 + hc + e];
                float cprev = e ? cp.y : cp.x;
                float c_new = sigm(fg) * cprev + sigm(ig) * tanhf(gg);
                float h_new = sigm(og) * tanhf(c_new);
                cn[e] = c_new; hn[e] = h_new;
            }
            if (LAYER == 1) {
                float2 rd = *(const float2*)&g_h0[pp ^ 1][base];
                hn[0] += rd.x; hn[1] += rd.y;
            }
            *(float2*)&cst[base]  = make_float2(cn[0], cn[1]);
            *(float2*)&hdst[base] = make_float2(hn[0], hn[1]);
            if (LAYER == 1) {
                size_t ob = (((size_t)b * NSEQ + t) * NNOD + n) * HD + hc;
                *(float2*)&out[ob] = make_float2(hn[0], hn[1]);
            }
            hv[a][j2][0] = hn[0]; hv[a][j2][1] = hn[1];
        }
    }

    if (LAYER == 0) {
        // LayerNorm over h (64 vals/row) via 4-lane (tig) shuffle groups -> z1
#pragma unroll
        for (int a = 0; a < 2; ++a) {
            float s1 = 0.f, s2 = 0.f;
#pragma unroll
            for (int j2 = 0; j2 < 8; ++j2) {
                s1 += hv[a][j2][0] + hv[a][j2][1];
                s2 += hv[a][j2][0] * hv[a][j2][0] + hv[a][j2][1] * hv[a][j2][1];
            }
            s1 += __shfl_xor_sync(0xffffffffu, s1, 1);
            s1 += __shfl_xor_sync(0xffffffffu, s1, 2);
            s2 += __shfl_xor_sync(0xffffffffu, s2, 1);
            s2 += __shfl_xor_sync(0xffffffffu, s2, 2);
            float mean = s1 * (1.0f / 64.0f);
            float var  = s2 * (1.0f / 64.0f) - mean * mean;
            float rs = rsqrtf(var + 1e-5f);
            int r = w2row + gid + a * 8;
            int n = m0 + r;
#pragma unroll
            for (int j2 = 0; j2 < 8; ++j2) {
                int hc = j2 * 8 + tig * 2;
                float2 ne = *(const float2*)&nemb[n * HD + hc];
                float z0v = (hv[a][j2][0] - mean) * rs * sm[OFF_PRM + 256 + hc]
                            + sm[OFF_PRM + 320 + hc] + ne.x;
                float z1v = (hv[a][j2][1] - mean) * rs * sm[OFF_PRM + 256 + hc + 1]
                            + sm[OFF_PRM + 320 + hc + 1] + ne.y;
                *(float2*)&g_z1[((size_t)n * NBAT + b) * HD + hc] = make_float2(z0v, z1v);
            }
        }
    }
}

// ---------------------------------------------------------------------------
// Launch
// ---------------------------------------------------------------------------
extern "C" void kernel_launch(void* const* d_in, const int* in_sizes, int n_in,
                              void* d_out, int out_size) {
    (void)in_sizes; (void)n_in; (void)out_size;
    const float* x    = (const float*)d_in[0];
    const float* adj  = (const float*)d_in[1];
    const float* Win  = (const float*)d_in[2];
    const float* bin  = (const float*)d_in[3];
    const float* nemb = (const float*)d_in[4];
    const float* gam  = (const float*)d_in[5];
    const float* bet  = (const float*)d_in[6];
    const float* Wg   = (const float*)d_in[7];
    const float* bg   = (const float*)d_in[8];
    float* out = (float*)d_out;

    cudaFuncSetAttribute((const void*)layer_kernel<0>,
                         cudaFuncAttributeMaxDynamicSharedMemorySize, SMEMB);
    cudaFuncSetAttribute((const void*)layer_kernel<1>,
                         cudaFuncAttributeMaxDynamicSharedMemorySize, SMEMB);

    adj_norm_kernel<<<NNOD, 256>>>(adj);
    wgcvt_kernel<<<(2 * 128 * 256) / 256, 256>>>(Wg);
    zero_kernel<<<TOT / 256, 256>>>();
    proj_kernel<<<(NBAT * NSEQ * NNOD) / 8, 256>>>(x, Win, bin, nemb, gam, bet);

    dim3 grid(8, NBAT);
    for (int t = 0; t < NSEQ; ++t) {
        int pp = t & 1;
        layer_kernel<0><<<grid, 256, SMEMB>>>(t, pp, bg, gam, bet, nemb, out);
        layer_kernel<1><<<grid, 256, SMEMB>>>(t, pp, bg, gam, bet, nemb, out);
    }
}